// round 14
// baseline (speedup 1.0000x reference)
#include <cuda_runtime.h>
#include <cuda_fp16.h>
#include <cstdint>

#define BB 8
#define SS 1024
#define FEAT 1024
#define HIDD 1024
#define HH 8
#define DHH 128
#define MTOT (BB*SS)
#define W2R 512      // f16x2 words per token row (HIDD/2)

// f16-fragment-permuted operands for the QKV GEMM (m16n8k16 layout)
__device__ uint32_t g_Ap[MTOT/16 * FEAT/16 * 32 * 4];
__device__ uint32_t g_Wp[3][HIDD/16 * FEAT/16 * 32 * 4];
// f16x2-packed Q/K: [token][dim-pair word]
__device__ uint32_t g_Qh[MTOT*W2R];
__device__ uint32_t g_Kh[MTOT*W2R];
// V transposed into token-pair pairs: [bh][dim(128)][tokenpair(512)]
__device__ uint32_t g_Vt[BB*HH*DHH*512];

__device__ __forceinline__ uint32_t packh2(float lo, float hi) {
    __half2 h = __floats2half2_rn(lo, hi);
    return *(uint32_t*)&h;
}
__device__ __forceinline__ uint32_t smaddr(const void* p) {
    return (uint32_t)__cvta_generic_to_shared(p);
}

#define CP16(dst,src) asm volatile("cp.async.cg.shared.global [%0], [%1], 16;" :: "r"(dst), "l"(src))
#define CPCOMMIT()    asm volatile("cp.async.commit_group;")
#define CPWAIT(n)     asm volatile("cp.async.wait_group %0;" :: "n"(n))

#define LDSM4(r0,r1,r2,r3,addr) \
    asm volatile("ldmatrix.sync.aligned.m8n8.x4.shared.b16 {%0,%1,%2,%3}, [%4];" \
        : "=r"(r0), "=r"(r1), "=r"(r2), "=r"(r3) : "r"(addr))

__device__ __forceinline__ void mma16(float* d, uint32_t a0, uint32_t a1,
                                      uint32_t a2, uint32_t a3,
                                      uint32_t b0, uint32_t b1) {
    asm volatile(
        "mma.sync.aligned.m16n8k16.row.col.f32.f16.f16.f32 "
        "{%0,%1,%2,%3}, {%4,%5,%6,%7}, {%8,%9}, {%0,%1,%2,%3};"
        : "+f"(d[0]), "+f"(d[1]), "+f"(d[2]), "+f"(d[3])
        : "r"(a0), "r"(a1), "r"(a2), "r"(a3), "r"(b0), "r"(b1));
}

// ---------------------------------------------------------------------------
// Prep: A and W fragment-permute in one launch.
// Blocks [0,4096): A. Blocks [4096,5632): W (512 per z).
// ---------------------------------------------------------------------------
__global__ __launch_bounds__(256)
void prep_kernel(const float* __restrict__ A, const float* __restrict__ W0,
                 const float* __restrict__ W1, const float* __restrict__ W2)
{
    int bid = blockIdx.x;
    if (bid < 4096) {
        int idx = bid*256 + threadIdx.x;
        int lane = idx & 31;
        int kg   = (idx >> 5) & 63;
        int mblk = idx >> 11;
        int g = lane >> 2, t = lane & 3;
        int row = 16*mblk + g, col = 16*kg + 2*t;
        const float* p0 = A + (long)row*FEAT + col;
        const float* p1 = A + (long)(row + 8)*FEAT + col;
        uint4 o;
        o.x = packh2(p0[0], p0[1]);
        o.y = packh2(p1[0], p1[1]);
        o.z = packh2(p0[8], p0[9]);
        o.w = packh2(p1[8], p1[9]);
        *(uint4*)(g_Ap + (long)idx*4) = o;
    } else {
        int b2 = bid - 4096;
        int z = b2 >> 9;
        const float* W = (z == 0) ? W0 : (z == 1 ? W1 : W2);
        int idx = (b2 & 511)*256 + threadIdx.x;
        int lane = idx & 31;
        int kg   = (idx >> 5) & 63;
        int jp   = idx >> 11;
        int g = lane >> 2, t = lane & 3;
        int kr = 16*kg + 2*t;
        int n0 = 16*jp + g;
        uint4 o;
        o.x = packh2(W[(long)kr*HIDD + n0],       W[(long)(kr+1)*HIDD + n0]);
        o.y = packh2(W[(long)(kr+8)*HIDD + n0],   W[(long)(kr+9)*HIDD + n0]);
        o.z = packh2(W[(long)kr*HIDD + n0 + 8],   W[(long)(kr+1)*HIDD + n0 + 8]);
        o.w = packh2(W[(long)(kr+8)*HIDD + n0+8], W[(long)(kr+9)*HIDD + n0 + 8]);
        *(uint4*)(g_Wp[z] + (long)idx*4) = o;
    }
}

// ---------------------------------------------------------------------------
// Pass 1: QKV projection GEMM, f16 mma.m16n8k16.
// Block tile 256x128 (8 warps in 4x2 grid of 64x64 warp tiles), K-step 64,
// double-buffered cp.async. z==2 (V) epilogue transposes -> g_Vt directly.
// ---------------------------------------------------------------------------
#define QA_W  8192                         // A stage words (256x64 f16)
#define QB_W  4096                         // B stage words (128x64 f16)
#define QSTG_W (QA_W + QB_W)               // 12288 words = 48KB
#define GSM_BYTES (2*QSTG_W*4)             // 98304 B (>= V staging 66560)

__global__ __launch_bounds__(256)
void qkv_mma_kernel(const float* __restrict__ bq, const float* __restrict__ bk,
                    const float* __restrict__ bv)
{
    extern __shared__ uint32_t smg[];
    const int tid = threadIdx.x;
    const int w = tid >> 5, lane = tid & 31;
    const int g = lane >> 2, t = lane & 3;
    const int mw = (w & 3) * 64, nw = (w >> 2) * 64;   // warp tile origin
    const int row0 = blockIdx.y * 256, col0 = blockIdx.x * 128;
    const int mb0 = row0 >> 4, jp0 = col0 >> 4;
    const int z = blockIdx.z;

    const uint32_t* Wp = g_Wp[z];
    const float* bias  = (z == 0) ? bq : (z == 1 ? bk : bv);

    float acc[4][8][4];
#pragma unroll
    for (int i = 0; i < 4; i++)
#pragma unroll
        for (int j = 0; j < 8; j++)
#pragma unroll
            for (int e = 0; e < 4; e++) acc[i][j][e] = 0.0f;

    // fill: A 2048 chunks (mblk 16 x kg 4 x lane 32), B 1024 chunks
    auto issue = [&](int it) {
        uint32_t base = smaddr(smg + (it & 1)*QSTG_W);
        int kg0 = it * 4;
#pragma unroll
        for (int i = 0; i < 8; i++) {
            int c = tid + i*256;                 // 0..2047
            int mloc = c >> 7, kgl = (c >> 5) & 3, lc = c & 31;
            CP16(base + c*16,
                 g_Ap + (((long)(mb0 + mloc)*64 + kg0 + kgl)*32 + lc)*4);
        }
        uint32_t baseB = base + QA_W*4;
#pragma unroll
        for (int i = 0; i < 4; i++) {
            int c = tid + i*256;                 // 0..1023
            int jloc = c >> 7, kgl = (c >> 5) & 3, lc = c & 31;
            CP16(baseB + c*16,
                 Wp + (((long)(jp0 + jloc)*64 + kg0 + kgl)*32 + lc)*4);
        }
    };

    issue(0); CPCOMMIT();
    for (int it = 0; it < 16; ++it) {
        if (it + 1 < 16) issue(it + 1);
        CPCOMMIT();
        CPWAIT(1);
        __syncthreads();
        const uint32_t* As = smg + (it & 1)*QSTG_W;
        const uint32_t* Bs = As + QA_W;
#pragma unroll
        for (int kgl = 0; kgl < 4; kgl++) {
            uint32_t a[4][4], b[4][4];
#pragma unroll
            for (int i = 0; i < 4; i++) {
                int mloc = (mw >> 4) + i;
                *(uint4*)a[i] = *(const uint4*)(As + ((mloc*4 + kgl)*32 + lane)*4);
            }
#pragma unroll
            for (int jp = 0; jp < 4; jp++) {
                int jloc = (nw >> 4) + jp;
                *(uint4*)b[jp] = *(const uint4*)(Bs + ((jloc*4 + kgl)*32 + lane)*4);
            }
#pragma unroll
            for (int i = 0; i < 4; i++)
#pragma unroll
                for (int jp = 0; jp < 4; jp++) {
                    mma16(acc[i][2*jp],     a[i][0], a[i][1], a[i][2], a[i][3],
                          b[jp][0], b[jp][1]);
                    mma16(acc[i][2*jp + 1], a[i][0], a[i][1], a[i][2], a[i][3],
                          b[jp][2], b[jp][3]);
                }
        }
        __syncthreads();
    }

    if (z < 2) {
        // Q/K epilogue: + bias, pack f16x2, store [token][dimpair]
        uint32_t* Og = (z == 0) ? g_Qh : g_Kh;
#pragma unroll
        for (int j = 0; j < 8; j++) {
            int col = col0 + nw + j*8 + 2*t;
            int colw = ((col0 + nw + j*8) >> 1) + t;
            float b0 = bias[col], b1 = bias[col + 1];
#pragma unroll
            for (int i = 0; i < 4; i++) {
                int row = row0 + mw + i*16 + g;
                Og[(long)row*W2R + colw]       = packh2(acc[i][j][0] + b0, acc[i][j][1] + b1);
                Og[(long)(row + 8)*W2R + colw] = packh2(acc[i][j][2] + b0, acc[i][j][3] + b1);
            }
        }
    } else {
        // V epilogue: stage [token_local(256)][dimpair(64)] in smem, write g_Vt
        uint32_t* sv = smg;                        // 256 x 65 words = 66560 B
        __syncthreads();
#pragma unroll
        for (int j = 0; j < 8; j++) {
            int col = col0 + nw + j*8 + 2*t;
            int dpl = ((nw + j*8) >> 1) + t;       // local dim-pair 0..63
            float b0 = bias[col], b1 = bias[col + 1];
#pragma unroll
            for (int i = 0; i < 4; i++) {
                int tokl = mw + i*16 + g;
                sv[tokl*65 + dpl]       = packh2(acc[i][j][0] + b0, acc[i][j][1] + b1);
                sv[(tokl + 8)*65 + dpl] = packh2(acc[i][j][2] + b0, acc[i][j][3] + b1);
            }
        }
        __syncthreads();

        const int b = row0 >> 10;                  // batch
        const int t0 = row0 & 1023;                // token offset within batch
        const int bh = b*HH + blockIdx.x;          // col block == head
        uint32_t* dst = g_Vt + ((long)bh*DHH)*512 + (t0 >> 1);
#pragma unroll
        for (int i = 0; i < 64; i++) {
            int idx = tid + i*256;                 // 0..16383
            int dim = idx >> 7, tpl = idx & 127;
            uint32_t w0 = sv[(2*tpl)*65 + (dim >> 1)];
            uint32_t w1 = sv[(2*tpl + 1)*65 + (dim >> 1)];
            uint32_t o = (dim & 1) ? __byte_perm(w0, w1, 0x7632)
                                   : __byte_perm(w0, w1, 0x5410);
            dst[(long)dim*512 + tpl] = o;
        }
    }
}

// ---------------------------------------------------------------------------
// Pass 2: causal attention (unchanged, measured 88.9us).
// ---------------------------------------------------------------------------
#define KH_STR 68
#define VT_STR 36
#define KTILE_W (64*KH_STR)
#define VTILE_W (128*VT_STR)
#define STAGE_W (KTILE_W + VTILE_W)
#define ASM_BYTES (2*STAGE_W*4)           // 71,680 B per CTA

__global__ __launch_bounds__(128, 2)
void attn_kernel(float* __restrict__ out)
{
    extern __shared__ uint32_t sm[];

    const int tid = threadIdx.x;
    const int w = tid >> 5, lane = tid & 31;
    const int g = lane >> 2, t = lane & 3;
    const int m0 = w * 16;
    const int qt = 15 - blockIdx.x;
    const int q0 = qt * 64;
    const int bh = blockIdx.y, b = bh >> 3, h = bh & 7;
    const int nk = qt + 1;

    const uint32_t* Qg = g_Qh + (long)b*SS*W2R + h*64;
    const uint32_t* Kg = g_Kh + (long)b*SS*W2R + h*64;
    const uint32_t* Vtg = g_Vt + (long)bh*DHH*512;

    const uint32_t kOff = (uint32_t)((((lane >> 4)*8 + (lane & 7))*KH_STR)*4
                                     + ((lane >> 3) & 1)*16);
    const uint32_t vOff = (uint32_t)((((lane >> 4)*8 + (lane & 7))*VT_STR)*4
                                     + ((lane >> 3) & 1)*16);
    const uint32_t aOff = (uint32_t)(((m0 + (lane & 7) + ((lane >> 3) & 1)*8)*KH_STR)*4
                                     + (lane >> 4)*16);

    {
        uint32_t base = smaddr(sm);
#pragma unroll
        for (int i = 0; i < 8; i++) {
            int c = tid + i*128;
            int r = c >> 4, part = c & 15;
            CP16(base + (r*KH_STR + part*4)*4, Qg + (long)(q0 + r)*W2R + part*4);
        }
        CPCOMMIT(); CPWAIT(0);
    }
    __syncthreads();

    uint32_t aQ[8][4];
    {
        uint32_t baseA = smaddr(sm) + aOff;
#pragma unroll
        for (int K = 0; K < 8; K++)
            LDSM4(aQ[K][0], aQ[K][1], aQ[K][2], aQ[K][3], baseA + K*32);
    }
    __syncthreads();

    float accO[16][4];
#pragma unroll
    for (int j = 0; j < 16; j++)
#pragma unroll
        for (int e = 0; e < 4; e++) accO[j][e] = 0.0f;
    float l0 = 0.0f, l1 = 0.0f;
    const float scl = 0.08838834764831843f;
    const float LN16 = 2.772588722239781f;

    auto issue = [&](int kt) {
        uint32_t baseK = smaddr(sm + (kt & 1)*STAGE_W);
        uint32_t baseV = baseK + KTILE_W*4;
        int k0 = kt * 64;
#pragma unroll
        for (int i = 0; i < 8; i++) {
            int c = tid + i*128;
            int r = c >> 4, part = c & 15;
            CP16(baseK + (r*KH_STR + part*4)*4, Kg + (long)(k0 + r)*W2R + part*4);
        }
#pragma unroll
        for (int i = 0; i < 8; i++) {
            int c = tid + i*128;
            int dim = c >> 3, part = c & 7;
            CP16(baseV + (dim*VT_STR + part*4)*4,
                 Vtg + (long)dim*512 + kt*32 + part*4);
        }
    };

    issue(0); CPCOMMIT();
    for (int kt = 0; kt < nk; kt++) {
        if (kt + 1 < nk) issue(kt + 1);
        CPCOMMIT();
        CPWAIT(1);
        __syncthreads();
        const uint32_t stg = smaddr(sm + (kt & 1)*STAGE_W);
        const uint32_t kBase = stg + kOff;
        const uint32_t vBase = stg + KTILE_W*4 + vOff;
        const int k0 = kt * 64;

        float s[8][4];
#pragma unroll
        for (int j = 0; j < 8; j++)
#pragma unroll
            for (int e = 0; e < 4; e++) s[j][e] = 0.0f;
#pragma unroll
        for (int K = 0; K < 8; K++) {
#pragma unroll
            for (int jp2 = 0; jp2 < 4; jp2++) {
                uint32_t b0, b1, b2, b3;
                LDSM4(b0, b1, b2, b3, kBase + jp2*(16*KH_STR*4) + K*32);
                mma16(s[2*jp2],     aQ[K][0], aQ[K][1], aQ[K][2], aQ[K][3], b0, b1);
                mma16(s[2*jp2 + 1], aQ[K][0], aQ[K][1], aQ[K][2], aQ[K][3], b2, b3);
            }
        }

        const int row_g  = q0 + m0 + g;
        const int row_g8 = row_g + 8;
        const bool diag = (k0 + 63 > row_g);
#pragma unroll
        for (int j = 0; j < 8; j++) {
            int c0 = k0 + j*8 + 2*t;
            float y0 = __expf(s[j][0]*scl), y1 = __expf(s[j][1]*scl);
            float y2 = __expf(s[j][2]*scl), y3 = __expf(s[j][3]*scl);
            float p0 = __expf(y0 - LN16), p1 = __expf(y1 - LN16);
            float p2 = __expf(y2 - LN16), p3 = __expf(y3 - LN16);
            if (diag) {
                if (c0     > row_g ) p0 = 0.0f;
                if (c0 + 1 > row_g ) p1 = 0.0f;
                if (c0     > row_g8) p2 = 0.0f;
                if (c0 + 1 > row_g8) p3 = 0.0f;
            }
            l0 += p0 + p1;
            l1 += p2 + p3;
            s[j][0] = p0; s[j][1] = p1; s[j][2] = p2; s[j][3] = p3;
        }

#pragma unroll
        for (int J = 0; J < 4; J++) {
            uint32_t a0 = packh2(s[2*J][0],     s[2*J][1]);
            uint32_t a1 = packh2(s[2*J][2],     s[2*J][3]);
            uint32_t a2 = packh2(s[2*J + 1][0], s[2*J + 1][1]);
            uint32_t a3 = packh2(s[2*J + 1][2], s[2*J + 1][3]);
#pragma unroll
            for (int jbp = 0; jbp < 8; jbp++) {
                uint32_t b0, b1, b2, b3;
                LDSM4(b0, b1, b2, b3, vBase + jbp*(16*VT_STR*4) + J*32);
                mma16(accO[2*jbp],     a0, a1, a2, a3, b0, b1);
                mma16(accO[2*jbp + 1], a0, a1, a2, a3, b2, b3);
            }
        }
        __syncthreads();
    }

    l0 += __shfl_xor_sync(0xffffffffu, l0, 1);
    l0 += __shfl_xor_sync(0xffffffffu, l0, 2);
    l1 += __shfl_xor_sync(0xffffffffu, l1, 1);
    l1 += __shfl_xor_sync(0xffffffffu, l1, 2);
    const float r0 = 1.0f / l0, r1 = 1.0f / l1;

    float* outp = out + ((long)b*SS + q0 + m0 + g)*HIDD + h*DHH;
#pragma unroll
    for (int j = 0; j < 16; j++) {
        int col = j*8 + 2*t;
        *(float2*)(outp + col)          = make_float2(accO[j][0]*r0, accO[j][1]*r0);
        *(float2*)(outp + 8*HIDD + col) = make_float2(accO[j][2]*r1, accO[j][3]*r1);
    }
}

// ---------------------------------------------------------------------------
extern "C" void kernel_launch(void* const* d_in, const int* in_sizes, int n_in,
                              void* d_out, int out_size)
{
    const float* queries = (const float*)d_in[0];
    const float* Wq = (const float*)d_in[1];
    const float* bq = (const float*)d_in[2];
    const float* Wk = (const float*)d_in[3];
    const float* bk = (const float*)d_in[4];
    const float* Wv = (const float*)d_in[5];
    const float* bv = (const float*)d_in[6];
    float* out = (float*)d_out;

    cudaFuncSetAttribute(qkv_mma_kernel, cudaFuncAttributeMaxDynamicSharedMemorySize, GSM_BYTES);
    cudaFuncSetAttribute(attn_kernel, cudaFuncAttributeMaxDynamicSharedMemorySize, ASM_BYTES);

    prep_kernel<<<5632, 256>>>(queries, Wq, Wk, Wv);
    qkv_mma_kernel<<<dim3(8, 32, 3), 256, GSM_BYTES>>>(bq, bk, bv);
    attn_kernel<<<dim3(16, 64), 128, ASM_BYTES>>>(out);
}

// round 15
// speedup vs baseline: 1.1300x; 1.1300x over previous
#include <cuda_runtime.h>
#include <cuda_fp16.h>
#include <cstdint>

#define BB 8
#define SS 1024
#define FEAT 1024
#define HIDD 1024
#define HH 8
#define DHH 128
#define MTOT (BB*SS)
#define W2R 512      // f16x2 words per token row (HIDD/2)

// f16-fragment-permuted operands for the QKV GEMM (m16n8k16 layout)
__device__ uint32_t g_Ap[MTOT/16 * FEAT/16 * 32 * 4];
__device__ uint32_t g_Wp[3][HIDD/16 * FEAT/16 * 32 * 4];
// f16x2-packed Q/K: [token][dim-pair word]
__device__ uint32_t g_Qh[MTOT*W2R];
__device__ uint32_t g_Kh[MTOT*W2R];
// V transposed into token-pair pairs: [bh][dim(128)][tokenpair(512)]
__device__ uint32_t g_Vt[BB*HH*DHH*512];

__device__ __forceinline__ uint32_t packh2(float lo, float hi) {
    __half2 h = __floats2half2_rn(lo, hi);
    return *(uint32_t*)&h;
}
__device__ __forceinline__ uint32_t smaddr(const void* p) {
    return (uint32_t)__cvta_generic_to_shared(p);
}

#define CP16(dst,src) asm volatile("cp.async.cg.shared.global [%0], [%1], 16;" :: "r"(dst), "l"(src))
#define CPCOMMIT()    asm volatile("cp.async.commit_group;")
#define CPWAIT(n)     asm volatile("cp.async.wait_group %0;" :: "n"(n))

#define LDSM4(r0,r1,r2,r3,addr) \
    asm volatile("ldmatrix.sync.aligned.m8n8.x4.shared.b16 {%0,%1,%2,%3}, [%4];" \
        : "=r"(r0), "=r"(r1), "=r"(r2), "=r"(r3) : "r"(addr))

__device__ __forceinline__ void mma16(float* d, uint32_t a0, uint32_t a1,
                                      uint32_t a2, uint32_t a3,
                                      uint32_t b0, uint32_t b1) {
    asm volatile(
        "mma.sync.aligned.m16n8k16.row.col.f32.f16.f16.f32 "
        "{%0,%1,%2,%3}, {%4,%5,%6,%7}, {%8,%9}, {%0,%1,%2,%3};"
        : "+f"(d[0]), "+f"(d[1]), "+f"(d[2]), "+f"(d[3])
        : "r"(a0), "r"(a1), "r"(a2), "r"(a3), "r"(b0), "r"(b1));
}

// ---------------------------------------------------------------------------
// Prep: A and W fragment-permute in one launch.
// ---------------------------------------------------------------------------
__global__ __launch_bounds__(256)
void prep_kernel(const float* __restrict__ A, const float* __restrict__ W0,
                 const float* __restrict__ W1, const float* __restrict__ W2)
{
    int bid = blockIdx.x;
    if (bid < 4096) {
        int idx = bid*256 + threadIdx.x;
        int lane = idx & 31;
        int kg   = (idx >> 5) & 63;
        int mblk = idx >> 11;
        int g = lane >> 2, t = lane & 3;
        int row = 16*mblk + g, col = 16*kg + 2*t;
        const float* p0 = A + (long)row*FEAT + col;
        const float* p1 = A + (long)(row + 8)*FEAT + col;
        uint4 o;
        o.x = packh2(p0[0], p0[1]);
        o.y = packh2(p1[0], p1[1]);
        o.z = packh2(p0[8], p0[9]);
        o.w = packh2(p1[8], p1[9]);
        *(uint4*)(g_Ap + (long)idx*4) = o;
    } else {
        int b2 = bid - 4096;
        int z = b2 >> 9;
        const float* W = (z == 0) ? W0 : (z == 1 ? W1 : W2);
        int idx = (b2 & 511)*256 + threadIdx.x;
        int lane = idx & 31;
        int kg   = (idx >> 5) & 63;
        int jp   = idx >> 11;
        int g = lane >> 2, t = lane & 3;
        int kr = 16*kg + 2*t;
        int n0 = 16*jp + g;
        uint4 o;
        o.x = packh2(W[(long)kr*HIDD + n0],       W[(long)(kr+1)*HIDD + n0]);
        o.y = packh2(W[(long)(kr+8)*HIDD + n0],   W[(long)(kr+9)*HIDD + n0]);
        o.z = packh2(W[(long)kr*HIDD + n0 + 8],   W[(long)(kr+1)*HIDD + n0 + 8]);
        o.w = packh2(W[(long)(kr+8)*HIDD + n0+8], W[(long)(kr+9)*HIDD + n0 + 8]);
        *(uint4*)(g_Wp[z] + (long)idx*4) = o;
    }
}

// ---------------------------------------------------------------------------
// Pass 1: QKV projection GEMM, f16 mma.m16n8k16.
// R13 shape (128 threads, 4 warps x 64x64, K-step 32), NOW 4-stage cp.async
// pipeline with a single barrier per iteration.
// z==2 (V) epilogue transposes in smem -> g_Vt directly.
// ---------------------------------------------------------------------------
#define QSTG_W 4096                       // words per stage (A 2048 + B 2048)
#define GSM_BYTES (4*QSTG_W*4)            // 65536 B (>= V staging 33280)

__global__ __launch_bounds__(128)
void qkv_mma_kernel(const float* __restrict__ bq, const float* __restrict__ bk,
                    const float* __restrict__ bv)
{
    extern __shared__ uint32_t smg[];
    const int tid = threadIdx.x;
    const int w = tid >> 5, lane = tid & 31;
    const int g = lane >> 2, t = lane & 3;
    const int mw = (w >> 1) * 64, nw = (w & 1) * 64;
    const int row0 = blockIdx.y * 128, col0 = blockIdx.x * 128;
    const int mb0 = row0 >> 4, jp0 = col0 >> 4;
    const int z = blockIdx.z;

    const uint32_t* Wp = g_Wp[z];
    const float* bias  = (z == 0) ? bq : (z == 1 ? bk : bv);

    float acc[4][8][4];
#pragma unroll
    for (int i = 0; i < 4; i++)
#pragma unroll
        for (int j = 0; j < 8; j++)
#pragma unroll
            for (int e = 0; e < 4; e++) acc[i][j][e] = 0.0f;

    auto issue = [&](int it) {
        uint32_t base = smaddr(smg + (it & 3)*QSTG_W);
        int kg0 = it * 2;
#pragma unroll
        for (int i = 0; i < 4; i++) {
            int c = tid + i*128;
            int mloc = c >> 6, kgl = (c >> 5) & 1, lc = c & 31;
            CP16(base + c*16,
                 g_Ap + (((long)(mb0 + mloc)*64 + kg0 + kgl)*32 + lc)*4);
        }
        uint32_t baseB = base + 2048*4;
#pragma unroll
        for (int i = 0; i < 4; i++) {
            int c = tid + i*128;
            int jloc = c >> 6, kgl = (c >> 5) & 1, lc = c & 31;
            CP16(baseB + c*16,
                 Wp + (((long)(jp0 + jloc)*64 + kg0 + kgl)*32 + lc)*4);
        }
    };

    issue(0); CPCOMMIT();
    issue(1); CPCOMMIT();
    issue(2); CPCOMMIT();
    for (int it = 0; it < 32; ++it) {
        CPWAIT(2);                     // stage `it` landed (this thread)
        __syncthreads();               // whole stage visible; prev reads done
        const uint32_t* As = smg + (it & 3)*QSTG_W;
        const uint32_t* Bs = As + 2048;
#pragma unroll
        for (int kgl = 0; kgl < 2; kgl++) {
            uint32_t a[4][4], b[4][4];
#pragma unroll
            for (int i = 0; i < 4; i++) {
                int mloc = (mw >> 4) + i;
                *(uint4*)a[i] = *(const uint4*)(As + ((mloc*2 + kgl)*32 + lane)*4);
            }
#pragma unroll
            for (int jp = 0; jp < 4; jp++) {
                int jloc = (nw >> 4) + jp;
                *(uint4*)b[jp] = *(const uint4*)(Bs + ((jloc*2 + kgl)*32 + lane)*4);
            }
#pragma unroll
            for (int i = 0; i < 4; i++)
#pragma unroll
                for (int jp = 0; jp < 4; jp++) {
                    mma16(acc[i][2*jp],     a[i][0], a[i][1], a[i][2], a[i][3],
                          b[jp][0], b[jp][1]);
                    mma16(acc[i][2*jp + 1], a[i][0], a[i][1], a[i][2], a[i][3],
                          b[jp][2], b[jp][3]);
                }
        }
        if (it + 3 < 32) issue(it + 3);
        CPCOMMIT();
    }

    if (z < 2) {
        // Q/K epilogue: + bias, pack f16x2, store [token][dimpair]
        uint32_t* Og = (z == 0) ? g_Qh : g_Kh;
#pragma unroll
        for (int j = 0; j < 8; j++) {
            int col = col0 + nw + j*8 + 2*t;
            int colw = ((col0 + nw + j*8) >> 1) + t;
            float b0 = bias[col], b1 = bias[col + 1];
#pragma unroll
            for (int i = 0; i < 4; i++) {
                int row = row0 + mw + i*16 + g;
                Og[(long)row*W2R + colw]       = packh2(acc[i][j][0] + b0, acc[i][j][1] + b1);
                Og[(long)(row + 8)*W2R + colw] = packh2(acc[i][j][2] + b0, acc[i][j][3] + b1);
            }
        }
    } else {
        // V epilogue: stage [token_local][dimpair] in smem, write g_Vt
        uint32_t* sv = smg;                        // 128 x 65 words
        __syncthreads();                           // mainloop reads done
#pragma unroll
        for (int j = 0; j < 8; j++) {
            int col = col0 + nw + j*8 + 2*t;
            int dpl = ((nw + j*8) >> 1) + t;       // local dim-pair 0..63
            float b0 = bias[col], b1 = bias[col + 1];
#pragma unroll
            for (int i = 0; i < 4; i++) {
                int tokl = mw + i*16 + g;
                sv[tokl*65 + dpl]       = packh2(acc[i][j][0] + b0, acc[i][j][1] + b1);
                sv[(tokl + 8)*65 + dpl] = packh2(acc[i][j][2] + b0, acc[i][j][3] + b1);
            }
        }
        __syncthreads();

        const int b = row0 >> 10;                  // batch
        const int t0 = row0 & 1023;                // token offset within batch
        const int bh = b*HH + blockIdx.x;          // col block == head
        uint32_t* dst = g_Vt + ((long)bh*DHH)*512 + (t0 >> 1);
#pragma unroll
        for (int i = 0; i < 64; i++) {
            int idx = tid + i*128;                 // 0..8191
            int dim = idx >> 6, tpl = idx & 63;
            uint32_t w0 = sv[(2*tpl)*65 + (dim >> 1)];
            uint32_t w1 = sv[(2*tpl + 1)*65 + (dim >> 1)];
            uint32_t o = (dim & 1) ? __byte_perm(w0, w1, 0x7632)
                                   : __byte_perm(w0, w1, 0x5410);
            dst[(long)dim*512 + tpl] = o;
        }
    }
}

// ---------------------------------------------------------------------------
// Pass 2: causal attention (unchanged, measured 88.9us).
// ---------------------------------------------------------------------------
#define KH_STR 68
#define VT_STR 36
#define KTILE_W (64*KH_STR)
#define VTILE_W (128*VT_STR)
#define STAGE_W (KTILE_W + VTILE_W)
#define ASM_BYTES (2*STAGE_W*4)           // 71,680 B per CTA

__global__ __launch_bounds__(128, 2)
void attn_kernel(float* __restrict__ out)
{
    extern __shared__ uint32_t sm[];

    const int tid = threadIdx.x;
    const int w = tid >> 5, lane = tid & 31;
    const int g = lane >> 2, t = lane & 3;
    const int m0 = w * 16;
    const int qt = 15 - blockIdx.x;
    const int q0 = qt * 64;
    const int bh = blockIdx.y, b = bh >> 3, h = bh & 7;
    const int nk = qt + 1;

    const uint32_t* Qg = g_Qh + (long)b*SS*W2R + h*64;
    const uint32_t* Kg = g_Kh + (long)b*SS*W2R + h*64;
    const uint32_t* Vtg = g_Vt + (long)bh*DHH*512;

    const uint32_t kOff = (uint32_t)((((lane >> 4)*8 + (lane & 7))*KH_STR)*4
                                     + ((lane >> 3) & 1)*16);
    const uint32_t vOff = (uint32_t)((((lane >> 4)*8 + (lane & 7))*VT_STR)*4
                                     + ((lane >> 3) & 1)*16);
    const uint32_t aOff = (uint32_t)(((m0 + (lane & 7) + ((lane >> 3) & 1)*8)*KH_STR)*4
                                     + (lane >> 4)*16);

    {
        uint32_t base = smaddr(sm);
#pragma unroll
        for (int i = 0; i < 8; i++) {
            int c = tid + i*128;
            int r = c >> 4, part = c & 15;
            CP16(base + (r*KH_STR + part*4)*4, Qg + (long)(q0 + r)*W2R + part*4);
        }
        CPCOMMIT(); CPWAIT(0);
    }
    __syncthreads();

    uint32_t aQ[8][4];
    {
        uint32_t baseA = smaddr(sm) + aOff;
#pragma unroll
        for (int K = 0; K < 8; K++)
            LDSM4(aQ[K][0], aQ[K][1], aQ[K][2], aQ[K][3], baseA + K*32);
    }
    __syncthreads();

    float accO[16][4];
#pragma unroll
    for (int j = 0; j < 16; j++)
#pragma unroll
        for (int e = 0; e < 4; e++) accO[j][e] = 0.0f;
    float l0 = 0.0f, l1 = 0.0f;
    const float scl = 0.08838834764831843f;
    const float LN16 = 2.772588722239781f;

    auto issue = [&](int kt) {
        uint32_t baseK = smaddr(sm + (kt & 1)*STAGE_W);
        uint32_t baseV = baseK + KTILE_W*4;
        int k0 = kt * 64;
#pragma unroll
        for (int i = 0; i < 8; i++) {
            int c = tid + i*128;
            int r = c >> 4, part = c & 15;
            CP16(baseK + (r*KH_STR + part*4)*4, Kg + (long)(k0 + r)*W2R + part*4);
        }
#pragma unroll
        for (int i = 0; i < 8; i++) {
            int c = tid + i*128;
            int dim = c >> 3, part = c & 7;
            CP16(baseV + (dim*VT_STR + part*4)*4,
                 Vtg + (long)dim*512 + kt*32 + part*4);
        }
    };

    issue(0); CPCOMMIT();
    for (int kt = 0; kt < nk; kt++) {
        if (kt + 1 < nk) issue(kt + 1);
        CPCOMMIT();
        CPWAIT(1);
        __syncthreads();
        const uint32_t stg = smaddr(sm + (kt & 1)*STAGE_W);
        const uint32_t kBase = stg + kOff;
        const uint32_t vBase = stg + KTILE_W*4 + vOff;
        const int k0 = kt * 64;

        float s[8][4];
#pragma unroll
        for (int j = 0; j < 8; j++)
#pragma unroll
            for (int e = 0; e < 4; e++) s[j][e] = 0.0f;
#pragma unroll
        for (int K = 0; K < 8; K++) {
#pragma unroll
            for (int jp2 = 0; jp2 < 4; jp2++) {
                uint32_t b0, b1, b2, b3;
                LDSM4(b0, b1, b2, b3, kBase + jp2*(16*KH_STR*4) + K*32);
                mma16(s[2*jp2],     aQ[K][0], aQ[K][1], aQ[K][2], aQ[K][3], b0, b1);
                mma16(s[2*jp2 + 1], aQ[K][0], aQ[K][1], aQ[K][2], aQ[K][3], b2, b3);
            }
        }

        const int row_g  = q0 + m0 + g;
        const int row_g8 = row_g + 8;
        const bool diag = (k0 + 63 > row_g);
#pragma unroll
        for (int j = 0; j < 8; j++) {
            int c0 = k0 + j*8 + 2*t;
            float y0 = __expf(s[j][0]*scl), y1 = __expf(s[j][1]*scl);
            float y2 = __expf(s[j][2]*scl), y3 = __expf(s[j][3]*scl);
            float p0 = __expf(y0 - LN16), p1 = __expf(y1 - LN16);
            float p2 = __expf(y2 - LN16), p3 = __expf(y3 - LN16);
            if (diag) {
                if (c0     > row_g ) p0 = 0.0f;
                if (c0 + 1 > row_g ) p1 = 0.0f;
                if (c0     > row_g8) p2 = 0.0f;
                if (c0 + 1 > row_g8) p3 = 0.0f;
            }
            l0 += p0 + p1;
            l1 += p2 + p3;
            s[j][0] = p0; s[j][1] = p1; s[j][2] = p2; s[j][3] = p3;
        }

#pragma unroll
        for (int J = 0; J < 4; J++) {
            uint32_t a0 = packh2(s[2*J][0],     s[2*J][1]);
            uint32_t a1 = packh2(s[2*J][2],     s[2*J][3]);
            uint32_t a2 = packh2(s[2*J + 1][0], s[2*J + 1][1]);
            uint32_t a3 = packh2(s[2*J + 1][2], s[2*J + 1][3]);
#pragma unroll
            for (int jbp = 0; jbp < 8; jbp++) {
                uint32_t b0, b1, b2, b3;
                LDSM4(b0, b1, b2, b3, vBase + jbp*(16*VT_STR*4) + J*32);
                mma16(accO[2*jbp],     a0, a1, a2, a3, b0, b1);
                mma16(accO[2*jbp + 1], a0, a1, a2, a3, b2, b3);
            }
        }
        __syncthreads();
    }

    l0 += __shfl_xor_sync(0xffffffffu, l0, 1);
    l0 += __shfl_xor_sync(0xffffffffu, l0, 2);
    l1 += __shfl_xor_sync(0xffffffffu, l1, 1);
    l1 += __shfl_xor_sync(0xffffffffu, l1, 2);
    const float r0 = 1.0f / l0, r1 = 1.0f / l1;

    float* outp = out + ((long)b*SS + q0 + m0 + g)*HIDD + h*DHH;
#pragma unroll
    for (int j = 0; j < 16; j++) {
        int col = j*8 + 2*t;
        *(float2*)(outp + col)          = make_float2(accO[j][0]*r0, accO[j][1]*r0);
        *(float2*)(outp + 8*HIDD + col) = make_float2(accO[j][2]*r1, accO[j][3]*r1);
    }
}

// ---------------------------------------------------------------------------
extern "C" void kernel_launch(void* const* d_in, const int* in_sizes, int n_in,
                              void* d_out, int out_size)
{
    const float* queries = (const float*)d_in[0];
    const float* Wq = (const float*)d_in[1];
    const float* bq = (const float*)d_in[2];
    const float* Wk = (const float*)d_in[3];
    const float* bk = (const float*)d_in[4];
    const float* Wv = (const float*)d_in[5];
    const float* bv = (const float*)d_in[6];
    float* out = (float*)d_out;

    cudaFuncSetAttribute(qkv_mma_kernel, cudaFuncAttributeMaxDynamicSharedMemorySize, GSM_BYTES);
    cudaFuncSetAttribute(attn_kernel, cudaFuncAttributeMaxDynamicSharedMemorySize, ASM_BYTES);

    prep_kernel<<<5632, 256>>>(queries, Wq, Wk, Wv);
    qkv_mma_kernel<<<dim3(8, 64, 3), 128, GSM_BYTES>>>(bq, bk, bv);
    attn_kernel<<<dim3(16, 64), 128, ASM_BYTES>>>(out);
}

// round 16
// speedup vs baseline: 1.1557x; 1.0228x over previous
#include <cuda_runtime.h>
#include <cuda_fp16.h>
#include <cstdint>

#define BB 8
#define SS 1024
#define FEAT 1024
#define HIDD 1024
#define HH 8
#define DHH 128
#define MTOT (BB*SS)
#define W2R 512      // f16x2 words per token row (HIDD/2)

// f16-fragment-permuted operands for the QKV GEMM (m16n8k16 layout)
__device__ uint32_t g_Ap[MTOT/16 * FEAT/16 * 32 * 4];
__device__ uint32_t g_Wp[3][HIDD/16 * FEAT/16 * 32 * 4];
// f16x2-packed Q/K: [token][dim-pair word]
__device__ uint32_t g_Qh[MTOT*W2R];
__device__ uint32_t g_Kh[MTOT*W2R];
// V transposed into token-pair pairs: [bh][dim(128)][tokenpair(512)]
__device__ uint32_t g_Vt[BB*HH*DHH*512];

__device__ __forceinline__ uint32_t packh2(float lo, float hi) {
    __half2 h = __floats2half2_rn(lo, hi);
    return *(uint32_t*)&h;
}
__device__ __forceinline__ uint32_t smaddr(const void* p) {
    return (uint32_t)__cvta_generic_to_shared(p);
}

#define CP16(dst,src) asm volatile("cp.async.cg.shared.global [%0], [%1], 16;" :: "r"(dst), "l"(src))
#define CPCOMMIT()    asm volatile("cp.async.commit_group;")
#define CPWAIT(n)     asm volatile("cp.async.wait_group %0;" :: "n"(n))

#define LDSM4(r0,r1,r2,r3,addr) \
    asm volatile("ldmatrix.sync.aligned.m8n8.x4.shared.b16 {%0,%1,%2,%3}, [%4];" \
        : "=r"(r0), "=r"(r1), "=r"(r2), "=r"(r3) : "r"(addr))

__device__ __forceinline__ void mma16(float* d, uint32_t a0, uint32_t a1,
                                      uint32_t a2, uint32_t a3,
                                      uint32_t b0, uint32_t b1) {
    asm volatile(
        "mma.sync.aligned.m16n8k16.row.col.f32.f16.f16.f32 "
        "{%0,%1,%2,%3}, {%4,%5,%6,%7}, {%8,%9}, {%0,%1,%2,%3};"
        : "+f"(d[0]), "+f"(d[1]), "+f"(d[2]), "+f"(d[3])
        : "r"(a0), "r"(a1), "r"(a2), "r"(a3), "r"(b0), "r"(b1));
}

// ---------------------------------------------------------------------------
// Prep: A and W fragment-permute in one launch (unchanged).
// ---------------------------------------------------------------------------
__global__ __launch_bounds__(256)
void prep_kernel(const float* __restrict__ A, const float* __restrict__ W0,
                 const float* __restrict__ W1, const float* __restrict__ W2)
{
    int bid = blockIdx.x;
    if (bid < 4096) {
        int idx = bid*256 + threadIdx.x;
        int lane = idx & 31;
        int kg   = (idx >> 5) & 63;
        int mblk = idx >> 11;
        int g = lane >> 2, t = lane & 3;
        int row = 16*mblk + g, col = 16*kg + 2*t;
        const float* p0 = A + (long)row*FEAT + col;
        const float* p1 = A + (long)(row + 8)*FEAT + col;
        uint4 o;
        o.x = packh2(p0[0], p0[1]);
        o.y = packh2(p1[0], p1[1]);
        o.z = packh2(p0[8], p0[9]);
        o.w = packh2(p1[8], p1[9]);
        *(uint4*)(g_Ap + (long)idx*4) = o;
    } else {
        int b2 = bid - 4096;
        int z = b2 >> 9;
        const float* W = (z == 0) ? W0 : (z == 1 ? W1 : W2);
        int idx = (b2 & 511)*256 + threadIdx.x;
        int lane = idx & 31;
        int kg   = (idx >> 5) & 63;
        int jp   = idx >> 11;
        int g = lane >> 2, t = lane & 3;
        int kr = 16*kg + 2*t;
        int n0 = 16*jp + g;
        uint4 o;
        o.x = packh2(W[(long)kr*HIDD + n0],       W[(long)(kr+1)*HIDD + n0]);
        o.y = packh2(W[(long)(kr+8)*HIDD + n0],   W[(long)(kr+9)*HIDD + n0]);
        o.z = packh2(W[(long)kr*HIDD + n0 + 8],   W[(long)(kr+1)*HIDD + n0 + 8]);
        o.w = packh2(W[(long)(kr+8)*HIDD + n0+8], W[(long)(kr+9)*HIDD + n0 + 8]);
        *(uint4*)(g_Wp[z] + (long)idx*4) = o;
    }
}

// ---------------------------------------------------------------------------
// Pass 1: QKV projection GEMM (unchanged from R15: 128 threads, 4-stage
// pipeline, single barrier). z==2 (V) epilogue -> g_Vt directly.
// ---------------------------------------------------------------------------
#define QSTG_W 4096
#define GSM_BYTES (4*QSTG_W*4)            // 65536 B

__global__ __launch_bounds__(128)
void qkv_mma_kernel(const float* __restrict__ bq, const float* __restrict__ bk,
                    const float* __restrict__ bv)
{
    extern __shared__ uint32_t smg[];
    const int tid = threadIdx.x;
    const int w = tid >> 5, lane = tid & 31;
    const int g = lane >> 2, t = lane & 3;
    const int mw = (w >> 1) * 64, nw = (w & 1) * 64;
    const int row0 = blockIdx.y * 128, col0 = blockIdx.x * 128;
    const int mb0 = row0 >> 4, jp0 = col0 >> 4;
    const int z = blockIdx.z;

    const uint32_t* Wp = g_Wp[z];
    const float* bias  = (z == 0) ? bq : (z == 1 ? bk : bv);

    float acc[4][8][4];
#pragma unroll
    for (int i = 0; i < 4; i++)
#pragma unroll
        for (int j = 0; j < 8; j++)
#pragma unroll
            for (int e = 0; e < 4; e++) acc[i][j][e] = 0.0f;

    auto issue = [&](int it) {
        uint32_t base = smaddr(smg + (it & 3)*QSTG_W);
        int kg0 = it * 2;
#pragma unroll
        for (int i = 0; i < 4; i++) {
            int c = tid + i*128;
            int mloc = c >> 6, kgl = (c >> 5) & 1, lc = c & 31;
            CP16(base + c*16,
                 g_Ap + (((long)(mb0 + mloc)*64 + kg0 + kgl)*32 + lc)*4);
        }
        uint32_t baseB = base + 2048*4;
#pragma unroll
        for (int i = 0; i < 4; i++) {
            int c = tid + i*128;
            int jloc = c >> 6, kgl = (c >> 5) & 1, lc = c & 31;
            CP16(baseB + c*16,
                 Wp + (((long)(jp0 + jloc)*64 + kg0 + kgl)*32 + lc)*4);
        }
    };

    issue(0); CPCOMMIT();
    issue(1); CPCOMMIT();
    issue(2); CPCOMMIT();
    for (int it = 0; it < 32; ++it) {
        CPWAIT(2);
        __syncthreads();
        const uint32_t* As = smg + (it & 3)*QSTG_W;
        const uint32_t* Bs = As + 2048;
#pragma unroll
        for (int kgl = 0; kgl < 2; kgl++) {
            uint32_t a[4][4], b[4][4];
#pragma unroll
            for (int i = 0; i < 4; i++) {
                int mloc = (mw >> 4) + i;
                *(uint4*)a[i] = *(const uint4*)(As + ((mloc*2 + kgl)*32 + lane)*4);
            }
#pragma unroll
            for (int jp = 0; jp < 4; jp++) {
                int jloc = (nw >> 4) + jp;
                *(uint4*)b[jp] = *(const uint4*)(Bs + ((jloc*2 + kgl)*32 + lane)*4);
            }
#pragma unroll
            for (int i = 0; i < 4; i++)
#pragma unroll
                for (int jp = 0; jp < 4; jp++) {
                    mma16(acc[i][2*jp],     a[i][0], a[i][1], a[i][2], a[i][3],
                          b[jp][0], b[jp][1]);
                    mma16(acc[i][2*jp + 1], a[i][0], a[i][1], a[i][2], a[i][3],
                          b[jp][2], b[jp][3]);
                }
        }
        if (it + 3 < 32) issue(it + 3);
        CPCOMMIT();
    }

    if (z < 2) {
        uint32_t* Og = (z == 0) ? g_Qh : g_Kh;
#pragma unroll
        for (int j = 0; j < 8; j++) {
            int col = col0 + nw + j*8 + 2*t;
            int colw = ((col0 + nw + j*8) >> 1) + t;
            float b0 = bias[col], b1 = bias[col + 1];
#pragma unroll
            for (int i = 0; i < 4; i++) {
                int row = row0 + mw + i*16 + g;
                Og[(long)row*W2R + colw]       = packh2(acc[i][j][0] + b0, acc[i][j][1] + b1);
                Og[(long)(row + 8)*W2R + colw] = packh2(acc[i][j][2] + b0, acc[i][j][3] + b1);
            }
        }
    } else {
        uint32_t* sv = smg;                        // 128 x 65 words
        __syncthreads();
#pragma unroll
        for (int j = 0; j < 8; j++) {
            int col = col0 + nw + j*8 + 2*t;
            int dpl = ((nw + j*8) >> 1) + t;
            float b0 = bias[col], b1 = bias[col + 1];
#pragma unroll
            for (int i = 0; i < 4; i++) {
                int tokl = mw + i*16 + g;
                sv[tokl*65 + dpl]       = packh2(acc[i][j][0] + b0, acc[i][j][1] + b1);
                sv[(tokl + 8)*65 + dpl] = packh2(acc[i][j][2] + b0, acc[i][j][3] + b1);
            }
        }
        __syncthreads();

        const int b = row0 >> 10;
        const int t0 = row0 & 1023;
        const int bh = b*HH + blockIdx.x;
        uint32_t* dst = g_Vt + ((long)bh*DHH)*512 + (t0 >> 1);
#pragma unroll
        for (int i = 0; i < 64; i++) {
            int idx = tid + i*128;
            int dim = idx >> 6, tpl = idx & 63;
            uint32_t w0 = sv[(2*tpl)*65 + (dim >> 1)];
            uint32_t w1 = sv[(2*tpl + 1)*65 + (dim >> 1)];
            uint32_t o = (dim & 1) ? __byte_perm(w0, w1, 0x7632)
                                   : __byte_perm(w0, w1, 0x5410);
            dst[(long)dim*512 + tpl] = o;
        }
    }
}

// ---------------------------------------------------------------------------
// Pass 2: causal attention. NOW: 3-stage cp.async K/V pipeline, ONE barrier
// per ktile (issue kt+2 at loop bottom; stage (kt+2)%3 was read in kt-1,
// protected by this iteration's top barrier).
// ---------------------------------------------------------------------------
#define KH_STR 68
#define VT_STR 36
#define KTILE_W (64*KH_STR)
#define VTILE_W (128*VT_STR)
#define STAGE_W (KTILE_W + VTILE_W)
#define ASM_BYTES (3*STAGE_W*4)           // 107,520 B per CTA (2 CTAs/SM)

__global__ __launch_bounds__(128, 2)
void attn_kernel(float* __restrict__ out)
{
    extern __shared__ uint32_t sm[];

    const int tid = threadIdx.x;
    const int w = tid >> 5, lane = tid & 31;
    const int g = lane >> 2, t = lane & 3;
    const int m0 = w * 16;
    const int qt = 15 - blockIdx.x;
    const int q0 = qt * 64;
    const int bh = blockIdx.y, b = bh >> 3, h = bh & 7;
    const int nk = qt + 1;

    const uint32_t* Qg = g_Qh + (long)b*SS*W2R + h*64;
    const uint32_t* Kg = g_Kh + (long)b*SS*W2R + h*64;
    const uint32_t* Vtg = g_Vt + (long)bh*DHH*512;

    const uint32_t kOff = (uint32_t)((((lane >> 4)*8 + (lane & 7))*KH_STR)*4
                                     + ((lane >> 3) & 1)*16);
    const uint32_t vOff = (uint32_t)((((lane >> 4)*8 + (lane & 7))*VT_STR)*4
                                     + ((lane >> 3) & 1)*16);
    const uint32_t aOff = (uint32_t)(((m0 + (lane & 7) + ((lane >> 3) & 1)*8)*KH_STR)*4
                                     + (lane >> 4)*16);

    // stage Q tile [64 tok x 64 words] through stage-0 buffer
    {
        uint32_t base = smaddr(sm);
#pragma unroll
        for (int i = 0; i < 8; i++) {
            int c = tid + i*128;
            int r = c >> 4, part = c & 15;
            CP16(base + (r*KH_STR + part*4)*4, Qg + (long)(q0 + r)*W2R + part*4);
        }
        CPCOMMIT(); CPWAIT(0);
    }
    __syncthreads();

    uint32_t aQ[8][4];
    {
        uint32_t baseA = smaddr(sm) + aOff;
#pragma unroll
        for (int K = 0; K < 8; K++)
            LDSM4(aQ[K][0], aQ[K][1], aQ[K][2], aQ[K][3], baseA + K*32);
    }
    __syncthreads();

    float accO[16][4];
#pragma unroll
    for (int j = 0; j < 16; j++)
#pragma unroll
        for (int e = 0; e < 4; e++) accO[j][e] = 0.0f;
    float l0 = 0.0f, l1 = 0.0f;
    const float scl = 0.08838834764831843f;
    const float LN16 = 2.772588722239781f;

    auto issue = [&](int kt) {
        int stg3 = kt - (kt/3)*3;
        uint32_t baseK = smaddr(sm + stg3*STAGE_W);
        uint32_t baseV = baseK + KTILE_W*4;
        int k0 = kt * 64;
#pragma unroll
        for (int i = 0; i < 8; i++) {
            int c = tid + i*128;
            int r = c >> 4, part = c & 15;
            CP16(baseK + (r*KH_STR + part*4)*4, Kg + (long)(k0 + r)*W2R + part*4);
        }
#pragma unroll
        for (int i = 0; i < 8; i++) {
            int c = tid + i*128;
            int dim = c >> 3, part = c & 7;
            CP16(baseV + (dim*VT_STR + part*4)*4,
                 Vtg + (long)dim*512 + kt*32 + part*4);
        }
    };

    issue(0); CPCOMMIT();
    if (1 < nk) issue(1);
    CPCOMMIT();
    for (int kt = 0; kt < nk; kt++) {
        CPWAIT(1);                     // stage kt's group complete
        __syncthreads();               // visible to all; prev reads done
        int stg3 = kt - (kt/3)*3;
        const uint32_t stg = smaddr(sm + stg3*STAGE_W);
        const uint32_t kBase = stg + kOff;
        const uint32_t vBase = stg + KTILE_W*4 + vOff;
        const int k0 = kt * 64;

        float s[8][4];
#pragma unroll
        for (int j = 0; j < 8; j++)
#pragma unroll
            for (int e = 0; e < 4; e++) s[j][e] = 0.0f;
#pragma unroll
        for (int K = 0; K < 8; K++) {
#pragma unroll
            for (int jp2 = 0; jp2 < 4; jp2++) {
                uint32_t b0, b1, b2, b3;
                LDSM4(b0, b1, b2, b3, kBase + jp2*(16*KH_STR*4) + K*32);
                mma16(s[2*jp2],     aQ[K][0], aQ[K][1], aQ[K][2], aQ[K][3], b0, b1);
                mma16(s[2*jp2 + 1], aQ[K][0], aQ[K][1], aQ[K][2], aQ[K][3], b2, b3);
            }
        }

        const int row_g  = q0 + m0 + g;
        const int row_g8 = row_g + 8;
        const bool diag = (k0 + 63 > row_g);
#pragma unroll
        for (int j = 0; j < 8; j++) {
            int c0 = k0 + j*8 + 2*t;
            float y0 = __expf(s[j][0]*scl), y1 = __expf(s[j][1]*scl);
            float y2 = __expf(s[j][2]*scl), y3 = __expf(s[j][3]*scl);
            float p0 = __expf(y0 - LN16), p1 = __expf(y1 - LN16);
            float p2 = __expf(y2 - LN16), p3 = __expf(y3 - LN16);
            if (diag) {
                if (c0     > row_g ) p0 = 0.0f;
                if (c0 + 1 > row_g ) p1 = 0.0f;
                if (c0     > row_g8) p2 = 0.0f;
                if (c0 + 1 > row_g8) p3 = 0.0f;
            }
            l0 += p0 + p1;
            l1 += p2 + p3;
            s[j][0] = p0; s[j][1] = p1; s[j][2] = p2; s[j][3] = p3;
        }

#pragma unroll
        for (int J = 0; J < 4; J++) {
            uint32_t a0 = packh2(s[2*J][0],     s[2*J][1]);
            uint32_t a1 = packh2(s[2*J][2],     s[2*J][3]);
            uint32_t a2 = packh2(s[2*J + 1][0], s[2*J + 1][1]);
            uint32_t a3 = packh2(s[2*J + 1][2], s[2*J + 1][3]);
#pragma unroll
            for (int jbp = 0; jbp < 8; jbp++) {
                uint32_t b0, b1, b2, b3;
                LDSM4(b0, b1, b2, b3, vBase + jbp*(16*VT_STR*4) + J*32);
                mma16(accO[2*jbp],     a0, a1, a2, a3, b0, b1);
                mma16(accO[2*jbp + 1], a0, a1, a2, a3, b2, b3);
            }
        }
        if (kt + 2 < nk) issue(kt + 2);
        CPCOMMIT();
    }

    l0 += __shfl_xor_sync(0xffffffffu, l0, 1);
    l0 += __shfl_xor_sync(0xffffffffu, l0, 2);
    l1 += __shfl_xor_sync(0xffffffffu, l1, 1);
    l1 += __shfl_xor_sync(0xffffffffu, l1, 2);
    const float r0 = 1.0f / l0, r1 = 1.0f / l1;

    float* outp = out + ((long)b*SS + q0 + m0 + g)*HIDD + h*DHH;
#pragma unroll
    for (int j = 0; j < 16; j++) {
        int col = j*8 + 2*t;
        *(float2*)(outp + col)          = make_float2(accO[j][0]*r0, accO[j][1]*r0);
        *(float2*)(outp + 8*HIDD + col) = make_float2(accO[j][2]*r1, accO[j][3]*r1);
    }
}

// ---------------------------------------------------------------------------
extern "C" void kernel_launch(void* const* d_in, const int* in_sizes, int n_in,
                              void* d_out, int out_size)
{
    const float* queries = (const float*)d_in[0];
    const float* Wq = (const float*)d_in[1];
    const float* bq = (const float*)d_in[2];
    const float* Wk = (const float*)d_in[3];
    const float* bk = (const float*)d_in[4];
    const float* Wv = (const float*)d_in[5];
    const float* bv = (const float*)d_in[6];
    float* out = (float*)d_out;

    cudaFuncSetAttribute(qkv_mma_kernel, cudaFuncAttributeMaxDynamicSharedMemorySize, GSM_BYTES);
    cudaFuncSetAttribute(attn_kernel, cudaFuncAttributeMaxDynamicSharedMemorySize, ASM_BYTES);

    prep_kernel<<<5632, 256>>>(queries, Wq, Wk, Wv);
    qkv_mma_kernel<<<dim3(8, 64, 3), 128, GSM_BYTES>>>(bq, bk, bv);
    attn_kernel<<<dim3(16, 64), 128, ASM_BYTES>>>(out);
}

// round 17
// speedup vs baseline: 1.1721x; 1.0142x over previous
#include <cuda_runtime.h>
#include <cuda_fp16.h>
#include <cstdint>

#define BB 8
#define SS 1024
#define FEAT 1024
#define HIDD 1024
#define HH 8
#define DHH 128
#define MTOT (BB*SS)
#define W2R 512      // f16x2 words per token row (HIDD/2)

// f16-fragment-permuted operands for the QKV GEMM (m16n8k16 layout)
__device__ uint32_t g_Ap[MTOT/16 * FEAT/16 * 32 * 4];
__device__ uint32_t g_Wp[3][HIDD/16 * FEAT/16 * 32 * 4];
// f16x2-packed Q/K: [token][dim-pair word]  (Q pre-scaled by 1/sqrt(DH))
__device__ uint32_t g_Qh[MTOT*W2R];
__device__ uint32_t g_Kh[MTOT*W2R];
// V transposed into token-pair pairs: [bh][dim(128)][tokenpair(512)]
__device__ uint32_t g_Vt[BB*HH*DHH*512];

__device__ __forceinline__ uint32_t packh2(float lo, float hi) {
    __half2 h = __floats2half2_rn(lo, hi);
    return *(uint32_t*)&h;
}
__device__ __forceinline__ uint32_t smaddr(const void* p) {
    return (uint32_t)__cvta_generic_to_shared(p);
}

#define CP16(dst,src) asm volatile("cp.async.cg.shared.global [%0], [%1], 16;" :: "r"(dst), "l"(src))
#define CPCOMMIT()    asm volatile("cp.async.commit_group;")
#define CPWAIT(n)     asm volatile("cp.async.wait_group %0;" :: "n"(n))

#define LDSM4(r0,r1,r2,r3,addr) \
    asm volatile("ldmatrix.sync.aligned.m8n8.x4.shared.b16 {%0,%1,%2,%3}, [%4];" \
        : "=r"(r0), "=r"(r1), "=r"(r2), "=r"(r3) : "r"(addr))

__device__ __forceinline__ void mma16(float* d, uint32_t a0, uint32_t a1,
                                      uint32_t a2, uint32_t a3,
                                      uint32_t b0, uint32_t b1) {
    asm volatile(
        "mma.sync.aligned.m16n8k16.row.col.f32.f16.f16.f32 "
        "{%0,%1,%2,%3}, {%4,%5,%6,%7}, {%8,%9}, {%0,%1,%2,%3};"
        : "+f"(d[0]), "+f"(d[1]), "+f"(d[2]), "+f"(d[3])
        : "r"(a0), "r"(a1), "r"(a2), "r"(a3), "r"(b0), "r"(b1));
}

// ---------------------------------------------------------------------------
// Prep: A and W fragment-permute in one launch (unchanged).
// ---------------------------------------------------------------------------
__global__ __launch_bounds__(256)
void prep_kernel(const float* __restrict__ A, const float* __restrict__ W0,
                 const float* __restrict__ W1, const float* __restrict__ W2)
{
    int bid = blockIdx.x;
    if (bid < 4096) {
        int idx = bid*256 + threadIdx.x;
        int lane = idx & 31;
        int kg   = (idx >> 5) & 63;
        int mblk = idx >> 11;
        int g = lane >> 2, t = lane & 3;
        int row = 16*mblk + g, col = 16*kg + 2*t;
        const float* p0 = A + (long)row*FEAT + col;
        const float* p1 = A + (long)(row + 8)*FEAT + col;
        uint4 o;
        o.x = packh2(p0[0], p0[1]);
        o.y = packh2(p1[0], p1[1]);
        o.z = packh2(p0[8], p0[9]);
        o.w = packh2(p1[8], p1[9]);
        *(uint4*)(g_Ap + (long)idx*4) = o;
    } else {
        int b2 = bid - 4096;
        int z = b2 >> 9;
        const float* W = (z == 0) ? W0 : (z == 1 ? W1 : W2);
        int idx = (b2 & 511)*256 + threadIdx.x;
        int lane = idx & 31;
        int kg   = (idx >> 5) & 63;
        int jp   = idx >> 11;
        int g = lane >> 2, t = lane & 3;
        int kr = 16*kg + 2*t;
        int n0 = 16*jp + g;
        uint4 o;
        o.x = packh2(W[(long)kr*HIDD + n0],       W[(long)(kr+1)*HIDD + n0]);
        o.y = packh2(W[(long)(kr+8)*HIDD + n0],   W[(long)(kr+9)*HIDD + n0]);
        o.z = packh2(W[(long)kr*HIDD + n0 + 8],   W[(long)(kr+1)*HIDD + n0 + 8]);
        o.w = packh2(W[(long)(kr+8)*HIDD + n0+8], W[(long)(kr+9)*HIDD + n0 + 8]);
        *(uint4*)(g_Wp[z] + (long)idx*4) = o;
    }
}

// ---------------------------------------------------------------------------
// Pass 1: QKV projection GEMM (R15 form), NOW __launch_bounds__(128,3) for
// 3 CTAs/SM. Q epilogue pre-scales by 1/sqrt(DH). V epilogue -> g_Vt.
// ---------------------------------------------------------------------------
#define QSTG_W 4096
#define GSM_BYTES (4*QSTG_W*4)            // 65536 B

__global__ __launch_bounds__(128, 3)
void qkv_mma_kernel(const float* __restrict__ bq, const float* __restrict__ bk,
                    const float* __restrict__ bv)
{
    extern __shared__ uint32_t smg[];
    const int tid = threadIdx.x;
    const int w = tid >> 5, lane = tid & 31;
    const int g = lane >> 2, t = lane & 3;
    const int mw = (w >> 1) * 64, nw = (w & 1) * 64;
    const int row0 = blockIdx.y * 128, col0 = blockIdx.x * 128;
    const int mb0 = row0 >> 4, jp0 = col0 >> 4;
    const int z = blockIdx.z;

    const uint32_t* Wp = g_Wp[z];
    const float* bias  = (z == 0) ? bq : (z == 1 ? bk : bv);

    float acc[4][8][4];
#pragma unroll
    for (int i = 0; i < 4; i++)
#pragma unroll
        for (int j = 0; j < 8; j++)
#pragma unroll
            for (int e = 0; e < 4; e++) acc[i][j][e] = 0.0f;

    auto issue = [&](int it) {
        uint32_t base = smaddr(smg + (it & 3)*QSTG_W);
        int kg0 = it * 2;
#pragma unroll
        for (int i = 0; i < 4; i++) {
            int c = tid + i*128;
            int mloc = c >> 6, kgl = (c >> 5) & 1, lc = c & 31;
            CP16(base + c*16,
                 g_Ap + (((long)(mb0 + mloc)*64 + kg0 + kgl)*32 + lc)*4);
        }
        uint32_t baseB = base + 2048*4;
#pragma unroll
        for (int i = 0; i < 4; i++) {
            int c = tid + i*128;
            int jloc = c >> 6, kgl = (c >> 5) & 1, lc = c & 31;
            CP16(baseB + c*16,
                 Wp + (((long)(jp0 + jloc)*64 + kg0 + kgl)*32 + lc)*4);
        }
    };

    issue(0); CPCOMMIT();
    issue(1); CPCOMMIT();
    issue(2); CPCOMMIT();
    for (int it = 0; it < 32; ++it) {
        CPWAIT(2);
        __syncthreads();
        const uint32_t* As = smg + (it & 3)*QSTG_W;
        const uint32_t* Bs = As + 2048;
#pragma unroll
        for (int kgl = 0; kgl < 2; kgl++) {
            uint32_t a[4][4], b[4][4];
#pragma unroll
            for (int i = 0; i < 4; i++) {
                int mloc = (mw >> 4) + i;
                *(uint4*)a[i] = *(const uint4*)(As + ((mloc*2 + kgl)*32 + lane)*4);
            }
#pragma unroll
            for (int jp = 0; jp < 4; jp++) {
                int jloc = (nw >> 4) + jp;
                *(uint4*)b[jp] = *(const uint4*)(Bs + ((jloc*2 + kgl)*32 + lane)*4);
            }
#pragma unroll
            for (int i = 0; i < 4; i++)
#pragma unroll
                for (int jp = 0; jp < 4; jp++) {
                    mma16(acc[i][2*jp],     a[i][0], a[i][1], a[i][2], a[i][3],
                          b[jp][0], b[jp][1]);
                    mma16(acc[i][2*jp + 1], a[i][0], a[i][1], a[i][2], a[i][3],
                          b[jp][2], b[jp][3]);
                }
        }
        if (it + 3 < 32) issue(it + 3);
        CPCOMMIT();
    }

    if (z < 2) {
        uint32_t* Og = (z == 0) ? g_Qh : g_Kh;
        const float oscl = (z == 0) ? 0.08838834764831843f : 1.0f;  // 1/sqrt(128)
#pragma unroll
        for (int j = 0; j < 8; j++) {
            int col = col0 + nw + j*8 + 2*t;
            int colw = ((col0 + nw + j*8) >> 1) + t;
            float b0 = bias[col], b1 = bias[col + 1];
#pragma unroll
            for (int i = 0; i < 4; i++) {
                int row = row0 + mw + i*16 + g;
                Og[(long)row*W2R + colw] =
                    packh2((acc[i][j][0] + b0)*oscl, (acc[i][j][1] + b1)*oscl);
                Og[(long)(row + 8)*W2R + colw] =
                    packh2((acc[i][j][2] + b0)*oscl, (acc[i][j][3] + b1)*oscl);
            }
        }
    } else {
        uint32_t* sv = smg;                        // 128 x 65 words
        __syncthreads();
#pragma unroll
        for (int j = 0; j < 8; j++) {
            int col = col0 + nw + j*8 + 2*t;
            int dpl = ((nw + j*8) >> 1) + t;
            float b0 = bias[col], b1 = bias[col + 1];
#pragma unroll
            for (int i = 0; i < 4; i++) {
                int tokl = mw + i*16 + g;
                sv[tokl*65 + dpl]       = packh2(acc[i][j][0] + b0, acc[i][j][1] + b1);
                sv[(tokl + 8)*65 + dpl] = packh2(acc[i][j][2] + b0, acc[i][j][3] + b1);
            }
        }
        __syncthreads();

        const int b = row0 >> 10;
        const int t0 = row0 & 1023;
        const int bh = b*HH + blockIdx.x;
        uint32_t* dst = g_Vt + ((long)bh*DHH)*512 + (t0 >> 1);
#pragma unroll
        for (int i = 0; i < 64; i++) {
            int idx = tid + i*128;
            int dim = idx >> 6, tpl = idx & 63;
            uint32_t w0 = sv[(2*tpl)*65 + (dim >> 1)];
            uint32_t w1 = sv[(2*tpl + 1)*65 + (dim >> 1)];
            uint32_t o = (dim & 1) ? __byte_perm(w0, w1, 0x7632)
                                   : __byte_perm(w0, w1, 0x5410);
            dst[(long)dim*512 + tpl] = o;
        }
    }
}

// ---------------------------------------------------------------------------
// Pass 2: causal attention, 3-stage pipeline (R16 form); Q pre-scaled so the
// first exp takes S directly (32 fewer FMULs per thread per ktile).
// ---------------------------------------------------------------------------
#define KH_STR 68
#define VT_STR 36
#define KTILE_W (64*KH_STR)
#define VTILE_W (128*VT_STR)
#define STAGE_W (KTILE_W + VTILE_W)
#define ASM_BYTES (3*STAGE_W*4)           // 107,520 B per CTA (2 CTAs/SM)

__global__ __launch_bounds__(128, 2)
void attn_kernel(float* __restrict__ out)
{
    extern __shared__ uint32_t sm[];

    const int tid = threadIdx.x;
    const int w = tid >> 5, lane = tid & 31;
    const int g = lane >> 2, t = lane & 3;
    const int m0 = w * 16;
    const int qt = 15 - blockIdx.x;
    const int q0 = qt * 64;
    const int bh = blockIdx.y, b = bh >> 3, h = bh & 7;
    const int nk = qt + 1;

    const uint32_t* Qg = g_Qh + (long)b*SS*W2R + h*64;
    const uint32_t* Kg = g_Kh + (long)b*SS*W2R + h*64;
    const uint32_t* Vtg = g_Vt + (long)bh*DHH*512;

    const uint32_t kOff = (uint32_t)((((lane >> 4)*8 + (lane & 7))*KH_STR)*4
                                     + ((lane >> 3) & 1)*16);
    const uint32_t vOff = (uint32_t)((((lane >> 4)*8 + (lane & 7))*VT_STR)*4
                                     + ((lane >> 3) & 1)*16);
    const uint32_t aOff = (uint32_t)(((m0 + (lane & 7) + ((lane >> 3) & 1)*8)*KH_STR)*4
                                     + (lane >> 4)*16);

    {
        uint32_t base = smaddr(sm);
#pragma unroll
        for (int i = 0; i < 8; i++) {
            int c = tid + i*128;
            int r = c >> 4, part = c & 15;
            CP16(base + (r*KH_STR + part*4)*4, Qg + (long)(q0 + r)*W2R + part*4);
        }
        CPCOMMIT(); CPWAIT(0);
    }
    __syncthreads();

    uint32_t aQ[8][4];
    {
        uint32_t baseA = smaddr(sm) + aOff;
#pragma unroll
        for (int K = 0; K < 8; K++)
            LDSM4(aQ[K][0], aQ[K][1], aQ[K][2], aQ[K][3], baseA + K*32);
    }
    __syncthreads();

    float accO[16][4];
#pragma unroll
    for (int j = 0; j < 16; j++)
#pragma unroll
        for (int e = 0; e < 4; e++) accO[j][e] = 0.0f;
    float l0 = 0.0f, l1 = 0.0f;
    const float LN16 = 2.772588722239781f;

    auto issue = [&](int kt) {
        int stg3 = kt - (kt/3)*3;
        uint32_t baseK = smaddr(sm + stg3*STAGE_W);
        uint32_t baseV = baseK + KTILE_W*4;
        int k0 = kt * 64;
#pragma unroll
        for (int i = 0; i < 8; i++) {
            int c = tid + i*128;
            int r = c >> 4, part = c & 15;
            CP16(baseK + (r*KH_STR + part*4)*4, Kg + (long)(k0 + r)*W2R + part*4);
        }
#pragma unroll
        for (int i = 0; i < 8; i++) {
            int c = tid + i*128;
            int dim = c >> 3, part = c & 7;
            CP16(baseV + (dim*VT_STR + part*4)*4,
                 Vtg + (long)dim*512 + kt*32 + part*4);
        }
    };

    issue(0); CPCOMMIT();
    if (1 < nk) issue(1);
    CPCOMMIT();
    for (int kt = 0; kt < nk; kt++) {
        CPWAIT(1);
        __syncthreads();
        int stg3 = kt - (kt/3)*3;
        const uint32_t stg = smaddr(sm + stg3*STAGE_W);
        const uint32_t kBase = stg + kOff;
        const uint32_t vBase = stg + KTILE_W*4 + vOff;
        const int k0 = kt * 64;

        float s[8][4];
#pragma unroll
        for (int j = 0; j < 8; j++)
#pragma unroll
            for (int e = 0; e < 4; e++) s[j][e] = 0.0f;
#pragma unroll
        for (int K = 0; K < 8; K++) {
#pragma unroll
            for (int jp2 = 0; jp2 < 4; jp2++) {
                uint32_t b0, b1, b2, b3;
                LDSM4(b0, b1, b2, b3, kBase + jp2*(16*KH_STR*4) + K*32);
                mma16(s[2*jp2],     aQ[K][0], aQ[K][1], aQ[K][2], aQ[K][3], b0, b1);
                mma16(s[2*jp2 + 1], aQ[K][0], aQ[K][1], aQ[K][2], aQ[K][3], b2, b3);
            }
        }

        const int row_g  = q0 + m0 + g;
        const int row_g8 = row_g + 8;
        const bool diag = (k0 + 63 > row_g);
#pragma unroll
        for (int j = 0; j < 8; j++) {
            int c0 = k0 + j*8 + 2*t;
            float y0 = __expf(s[j][0]), y1 = __expf(s[j][1]);
            float y2 = __expf(s[j][2]), y3 = __expf(s[j][3]);
            float p0 = __expf(y0 - LN16), p1 = __expf(y1 - LN16);
            float p2 = __expf(y2 - LN16), p3 = __expf(y3 - LN16);
            if (diag) {
                if (c0     > row_g ) p0 = 0.0f;
                if (c0 + 1 > row_g ) p1 = 0.0f;
                if (c0     > row_g8) p2 = 0.0f;
                if (c0 + 1 > row_g8) p3 = 0.0f;
            }
            l0 += p0 + p1;
            l1 += p2 + p3;
            s[j][0] = p0; s[j][1] = p1; s[j][2] = p2; s[j][3] = p3;
        }

#pragma unroll
        for (int J = 0; J < 4; J++) {
            uint32_t a0 = packh2(s[2*J][0],     s[2*J][1]);
            uint32_t a1 = packh2(s[2*J][2],     s[2*J][3]);
            uint32_t a2 = packh2(s[2*J + 1][0], s[2*J + 1][1]);
            uint32_t a3 = packh2(s[2*J + 1][2], s[2*J + 1][3]);
#pragma unroll
            for (int jbp = 0; jbp < 8; jbp++) {
                uint32_t b0, b1, b2, b3;
                LDSM4(b0, b1, b2, b3, vBase + jbp*(16*VT_STR*4) + J*32);
                mma16(accO[2*jbp],     a0, a1, a2, a3, b0, b1);
                mma16(accO[2*jbp + 1], a0, a1, a2, a3, b2, b3);
            }
        }
        if (kt + 2 < nk) issue(kt + 2);
        CPCOMMIT();
    }

    l0 += __shfl_xor_sync(0xffffffffu, l0, 1);
    l0 += __shfl_xor_sync(0xffffffffu, l0, 2);
    l1 += __shfl_xor_sync(0xffffffffu, l1, 1);
    l1 += __shfl_xor_sync(0xffffffffu, l1, 2);
    const float r0 = 1.0f / l0, r1 = 1.0f / l1;

    float* outp = out + ((long)b*SS + q0 + m0 + g)*HIDD + h*DHH;
#pragma unroll
    for (int j = 0; j < 16; j++) {
        int col = j*8 + 2*t;
        *(float2*)(outp + col)          = make_float2(accO[j][0]*r0, accO[j][1]*r0);
        *(float2*)(outp + 8*HIDD + col) = make_float2(accO[j][2]*r1, accO[j][3]*r1);
    }
}

// ---------------------------------------------------------------------------
extern "C" void kernel_launch(void* const* d_in, const int* in_sizes, int n_in,
                              void* d_out, int out_size)
{
    const float* queries = (const float*)d_in[0];
    const float* Wq = (const float*)d_in[1];
    const float* bq = (const float*)d_in[2];
    const float* Wk = (const float*)d_in[3];
    const float* bk = (const float*)d_in[4];
    const float* Wv = (const float*)d_in[5];
    const float* bv = (const float*)d_in[6];
    float* out = (float*)d_out;

    cudaFuncSetAttribute(qkv_mma_kernel, cudaFuncAttributeMaxDynamicSharedMemorySize, GSM_BYTES);
    cudaFuncSetAttribute(attn_kernel, cudaFuncAttributeMaxDynamicSharedMemorySize, ASM_BYTES);

    prep_kernel<<<5632, 256>>>(queries, Wq, Wk, Wv);
    qkv_mma_kernel<<<dim3(8, 64, 3), 128, GSM_BYTES>>>(bq, bk, bv);
    attn_kernel<<<dim3(16, 64), 128, ASM_BYTES>>>(out);
}